// round 15
// baseline (speedup 1.0000x reference)
#include <cuda_runtime.h>
#include <cuda_fp16.h>
#include <math.h>
#include <stdint.h>

#define BT      8192
#define D_DIM   1024
#define E_NUM   8
#define H_DIM   4096
#define CAP     (2*BT)
#define NSLOT   (2*BT)

#define RB      (BT / 8)                                  // 1024 router blocks
#define W1T     (E_NUM * (D_DIM / 64) * (H_DIM / 32))     // 16384
#define W2T     (E_NUM * (H_DIM / 64) * (D_DIM / 32))     // 16384
#define ZYB     2048                                      // zero-y blocks (16KB each)

// ---------------- device scratch ----------------
__device__ __half g_x[(size_t)BT * D_DIM];
__device__ __half g_w1t[(size_t)E_NUM * H_DIM * D_DIM];
__device__ __half g_w2t[(size_t)E_NUM * D_DIM * H_DIM];
__device__ __half g_h[(size_t)NSLOT * H_DIM];
__device__ int   g_slots[E_NUM * CAP];
__device__ float g_gp[NSLOT];
__device__ int   g_cnt[E_NUM];
__device__ float g_imp[E_NUM];
__device__ int   g_loadc[E_NUM];

// ---------------- PTX helpers ----------------
__device__ __forceinline__ uint32_t smem_u32(const void* p) {
    return (uint32_t)__cvta_generic_to_shared(p);
}
__device__ __forceinline__ void cp_async16(uint32_t dst, const void* src) {
    asm volatile("cp.async.cg.shared.global [%0], [%1], 16;" :: "r"(dst), "l"(src));
}
#define CP_COMMIT() asm volatile("cp.async.commit_group;" ::: "memory")
#define CP_WAIT1()  asm volatile("cp.async.wait_group 1;" ::: "memory")

__device__ __forceinline__ void ldmatrix_x4(uint32_t* r, uint32_t addr) {
    asm volatile("ldmatrix.sync.aligned.m8n8.x4.shared.b16 {%0,%1,%2,%3}, [%4];"
        : "=r"(r[0]), "=r"(r[1]), "=r"(r[2]), "=r"(r[3]) : "r"(addr));
}
__device__ __forceinline__ void mma_16816(float* d, const uint32_t* a,
                                          uint32_t b0, uint32_t b1) {
    asm volatile(
        "mma.sync.aligned.m16n8k16.row.col.f32.f16.f16.f32 "
        "{%0,%1,%2,%3}, {%4,%5,%6,%7}, {%8,%9}, {%0,%1,%2,%3};"
        : "+f"(d[0]), "+f"(d[1]), "+f"(d[2]), "+f"(d[3])
        : "r"(a[0]), "r"(a[1]), "r"(a[2]), "r"(a[3]), "r"(b0), "r"(b1));
}
__device__ __forceinline__ void red_add_f32(float* addr, float v) {
    asm volatile("red.global.add.f32 [%0], %1;" :: "l"(addr), "f"(v) : "memory");
}

// ---------------- init ----------------
__global__ void init_kernel() {
    int i = threadIdx.x;
    if (i < E_NUM) { g_cnt[i] = 0; g_imp[i] = 0.f; g_loadc[i] = 0; }
}

// ---------------- generic 64k x 32n convert+transpose tile ----------------
__device__ __forceinline__ void conv_tile(const float* __restrict__ W,
                                          __half* __restrict__ Wt,
                                          int K, int N, int idx, float* tile) {
    int tid = threadIdx.x;
    int tilesK = K / 64;
    int e  = idx / (tilesK * (N / 32));
    int r  = idx % (tilesK * (N / 32));
    int k0 = (r % tilesK) * 64;
    int n0 = (r / tilesK) * 32;
    const float* Wb = W + (size_t)e * K * N;
#pragma unroll
    for (int j = 0; j < 8; j++) {
        int i = tid + 256 * j;
        int k = i >> 5, n = i & 31;
        tile[k * 33 + n] = Wb[(size_t)(k0 + k) * N + n0 + n];
    }
    __syncthreads();
    int nn = tid >> 3;
    int kc = (tid & 7) * 8;
    __half h[8];
#pragma unroll
    for (int q = 0; q < 8; q++) h[q] = __float2half_rn(tile[(kc + q) * 33 + nn]);
    size_t o = ((size_t)e * N + n0 + nn) * K + k0 + kc;
    *(uint4*)&Wt[o] = *(uint4*)&h[0];
}

// ---------------- prep: router | w1 conv | w2 conv | zero-y by block range ----------------
__global__ void __launch_bounds__(256) prep_kernel(const float* __restrict__ x,
                                                   const float* __restrict__ gW,
                                                   const float* __restrict__ w1,
                                                   const float* __restrict__ w2,
                                                   float* __restrict__ y) {
    __shared__ float sW[E_NUM][D_DIM];   // router weights / conv tile
    __shared__ float s_imp[E_NUM];
    __shared__ int   s_load[E_NUM];
    int tid = threadIdx.x;
    int bid = blockIdx.x;

    if (bid >= RB) {
        int r = bid - RB;
        if (r < W1T) {
            conv_tile(w1, g_w1t, D_DIM, H_DIM, r, &sW[0][0]);
        } else if (r < W1T + W2T) {
            conv_tile(w2, g_w2t, H_DIM, D_DIM, r - W1T, &sW[0][0]);
        } else {
            size_t base = (size_t)(r - W1T - W2T) * 4096;     // floats
            float4* y4 = (float4*)(y + base);
#pragma unroll
            for (int j = 0; j < 4; j++)
                y4[tid + 256 * j] = make_float4(0.f, 0.f, 0.f, 0.f);
        }
        return;
    }

    // ---- router (+ fused x->fp16) ----
    if (tid < E_NUM) { s_imp[tid] = 0.f; s_load[tid] = 0; }
    for (int i = tid; i < D_DIM * E_NUM; i += 256) {
        int d = i / E_NUM, e = i % E_NUM;
        sW[e][d] = gW[i];
    }
    __syncthreads();

    int warp = tid >> 5, lane = tid & 31;
    int t = bid * 8 + warp;
    const float* xr = x + (size_t)t * D_DIM;

    float acc[E_NUM];
#pragma unroll
    for (int e = 0; e < E_NUM; e++) acc[e] = 0.f;
    for (int d4 = lane; d4 < D_DIM / 4; d4 += 32) {
        float4 v = ((const float4*)xr)[d4];
        float f[4] = {v.x, v.y, v.z, v.w};
        __half h[4];
#pragma unroll
        for (int q = 0; q < 4; q++) {
            h[q] = __float2half_rn(f[q]);
#pragma unroll
            for (int e = 0; e < E_NUM; e++)
                acc[e] = fmaf(f[q], sW[e][d4 * 4 + q], acc[e]);
        }
        ((uint2*)g_x)[(size_t)t * (D_DIM / 4) + d4] = *(uint2*)&h[0];
    }
#pragma unroll
    for (int off = 16; off > 0; off >>= 1) {
#pragma unroll
        for (int e = 0; e < E_NUM; e++)
            acc[e] += __shfl_xor_sync(0xffffffffu, acc[e], off);
    }

    if (lane == 0) {
        float mx = acc[0];
#pragma unroll
        for (int e = 1; e < E_NUM; e++) mx = fmaxf(mx, acc[e]);
        float p[E_NUM], s = 0.f;
#pragma unroll
        for (int e = 0; e < E_NUM; e++) { p[e] = expf(acc[e] - mx); s += p[e]; }
        float inv = 1.f / s;
#pragma unroll
        for (int e = 0; e < E_NUM; e++) p[e] *= inv;

        int e1 = 0; float v1 = p[0];
#pragma unroll
        for (int e = 1; e < E_NUM; e++) if (p[e] > v1) { v1 = p[e]; e1 = e; }
        int e2 = -1; float v2 = -1.f;
#pragma unroll
        for (int e = 0; e < E_NUM; e++) if (e != e1 && p[e] > v2) { v2 = p[e]; e2 = e; }

        float ginv = 1.f / (v1 + v2);
        g_gp[2 * t]     = v1 * ginv;
        g_gp[2 * t + 1] = v2 * ginv;

        int p1 = atomicAdd(&g_cnt[e1], 1); g_slots[e1 * CAP + p1] = 2 * t;
        int p2 = atomicAdd(&g_cnt[e2], 1); g_slots[e2 * CAP + p2] = 2 * t + 1;
#pragma unroll
        for (int e = 0; e < E_NUM; e++) atomicAdd(&s_imp[e], p[e]);
        atomicAdd(&s_load[e1], 1);
    }
    __syncthreads();
    if (tid < E_NUM) {
        atomicAdd(&g_imp[tid], s_imp[tid]);
        atomicAdd(&g_loadc[tid], s_load[tid]);
    }
}

// ---------------- mma.sync grouped GEMM ----------------
// CTA tile 128x128, K-chunk 64, 3-stage cp.async (96KB), 2 CTAs/SM.
// KSPLIT-way split-K (gemm2 only; epilogue is REDG so splits just add).
template <int N_TOT, int K_SIZE, bool PHASE1, int KSPLIT>
__global__ void __launch_bounds__(256, 2) gemm_tc(const float* __restrict__ bias,
                                                  float* __restrict__ yout,
                                                  long long out_size) {
    int e   = blockIdx.z / KSPLIT;
    int kz  = blockIdx.z % KSPLIT;
    int cnt = g_cnt[e];
    int m0  = blockIdx.y * 128;
    int n0  = blockIdx.x * 128;
    int tid = threadIdx.x;

    // fold aux-loss write into one CTA of gemm2 (before any early exit)
    if (!PHASE1 && blockIdx.x == 0 && blockIdx.y == 0 && blockIdx.z == 0 && tid == 0) {
        float aux = 0.f;
        const float invBT = 1.f / (float)BT;
#pragma unroll
        for (int q = 0; q < E_NUM; q++)
            aux += (g_imp[q] * invBT) * ((float)g_loadc[q] * invBT);
        aux *= (float)E_NUM * 0.01f;
        yout[out_size - 1] = aux;
    }
    if (m0 >= cnt) return;

    constexpr int KLOC = K_SIZE / KSPLIT;

    extern __shared__ char smem[];
    uint32_t sb = smem_u32(smem);
    const int STAGE = 32768;
    const int AOF = 0, BOF = 16384;

    __shared__ int   sSlot[128];
    __shared__ float sBias[128];
    __shared__ float sGp[128];

    int lane = tid & 31;
    int w    = tid >> 5;
    int wm   = w >> 2;
    int wn   = w & 3;

    if (tid < 128) {
        int m = m0 + tid;
        int s = (m < cnt) ? g_slots[e * CAP + m] : -1;
        sSlot[tid] = s;
        sBias[tid] = (kz == 0) ? bias[(size_t)e * N_TOT + n0 + tid] : 0.f;
        if (!PHASE1) sGp[tid] = (s >= 0) ? g_gp[s] : 0.f;
    }
    __syncthreads();

    if (cnt - m0 < 128) {
#pragma unroll
        for (int s = 0; s < 3; s++) {
            uint32_t base = sb + s * STAGE + AOF;
            for (int off = tid * 16; off < 16384; off += 256 * 16)
                asm volatile("st.shared.v4.b32 [%0], {%1,%1,%1,%1};" :: "r"(base + off), "r"(0) : "memory");
        }
        __syncthreads();
    }

    const __half* Ap = PHASE1 ? g_x   : g_h;
    const __half* Bp = PHASE1 ? g_w1t : g_w2t;

    const char* aP[4];
    const char* bP[4];
    bool aval[4];
    uint32_t dsw[4];
    int colB = (tid & 7) * 16;
#pragma unroll
    for (int j = 0; j < 4; j++) {
        int row = (tid >> 3) + j * 32;
        int s   = sSlot[row];
        aval[j] = (s >= 0);
        size_t arow = 0;
        if (aval[j]) arow = PHASE1 ? (size_t)(s >> 1) : (size_t)s;
        aP[j] = (const char*)(Ap + arow * K_SIZE + kz * KLOC) + colB;
        size_t nrow = (size_t)e * N_TOT + n0 + row;
        bP[j] = (const char*)(Bp + nrow * K_SIZE + kz * KLOC) + colB;
        uint32_t off = (uint32_t)row * 128 + colB;
        dsw[j] = off ^ ((off >> 3) & 0x70);
    }

#define LOAD_CHUNK(c) do { \
        uint32_t base_ = sb + ((c) % 3) * STAGE; \
        size_t kb_ = (size_t)(c) * 128; \
        _Pragma("unroll") \
        for (int j = 0; j < 4; j++) { \
            if (aval[j]) cp_async16(base_ + AOF + dsw[j], aP[j] + kb_); \
            cp_async16(base_ + BOF + dsw[j], bP[j] + kb_); \
        } \
    } while (0)

    int lrow = ((lane >> 3) & 1) * 8 + (lane & 7);
    int lkb  = (lane >> 4) * 16;

    float acc[4][4][4];
#pragma unroll
    for (int i = 0; i < 4; i++)
#pragma unroll
        for (int j = 0; j < 4; j++)
#pragma unroll
            for (int q = 0; q < 4; q++) acc[i][j][q] = 0.f;

    constexpr int C = KLOC / 64;
    LOAD_CHUNK(0); CP_COMMIT();
    LOAD_CHUNK(1); CP_COMMIT();

    for (int c = 0; c < C; c++) {
        uint32_t base = sb + (c % 3) * STAGE;
        CP_WAIT1();
        __syncthreads();
        if (c + 2 < C) LOAD_CHUNK(c + 2);
        CP_COMMIT();

#pragma unroll
        for (int kk = 0; kk < 4; kk++) {
            int kb = kk * 32 + lkb;
            uint32_t ah[4][4];
#pragma unroll
            for (int mi = 0; mi < 4; mi++) {
                uint32_t off = (uint32_t)(wm * 64 + mi * 16 + lrow) * 128 + kb;
                uint32_t sw  = off ^ ((off >> 3) & 0x70);
                ldmatrix_x4(ah[mi], base + AOF + sw);
            }
            uint32_t bh[2][4];
#pragma unroll
            for (int ng = 0; ng < 2; ng++) {
                uint32_t off = (uint32_t)(wn * 32 + ng * 16 + lrow) * 128 + kb;
                uint32_t sw  = off ^ ((off >> 3) & 0x70);
                ldmatrix_x4(bh[ng], base + BOF + sw);
            }
#pragma unroll
            for (int mi = 0; mi < 4; mi++) {
#pragma unroll
                for (int ng = 0; ng < 2; ng++) {
#pragma unroll
                    for (int jj = 0; jj < 2; jj++) {
                        int nj = ng * 2 + jj;
                        mma_16816(acc[mi][nj], ah[mi], bh[ng][jj], bh[ng][jj + 2]);
                    }
                }
            }
        }
    }
#undef LOAD_CHUNK

    // ---------------- epilogue ----------------
#pragma unroll
    for (int mi = 0; mi < 4; mi++) {
#pragma unroll
        for (int h2 = 0; h2 < 2; h2++) {
            int rloc = wm * 64 + mi * 16 + h2 * 8 + (lane >> 2);
            int slot = sSlot[rloc];
            if (slot < 0) continue;
            float gp = PHASE1 ? 0.f : sGp[rloc];
#pragma unroll
            for (int nj = 0; nj < 4; nj++) {
                int cl = wn * 32 + nj * 8 + (lane & 3) * 2;
                float v0 = acc[mi][nj][h2 * 2 + 0] + sBias[cl];
                float v1 = acc[mi][nj][h2 * 2 + 1] + sBias[cl + 1];
                if (PHASE1) {
                    v0 = fmaxf(v0, 0.f);
                    v1 = fmaxf(v1, 0.f);
                    __half2 hp;
                    hp.x = __float2half_rn(v0);
                    hp.y = __float2half_rn(v1);
                    size_t bo = (size_t)slot * H_DIM + n0 + cl;
                    *(__half2*)&g_h[bo] = hp;
                } else {
                    size_t bo = (size_t)(slot >> 1) * D_DIM + n0 + cl;
                    red_add_f32(&yout[bo],     gp * v0);
                    red_add_f32(&yout[bo + 1], gp * v1);
                }
            }
        }
    }
}

// ---------------- launch ----------------
extern "C" void kernel_launch(void* const* d_in, const int* in_sizes, int n_in,
                              void* d_out, int out_size) {
    const float* x  = (const float*)d_in[0];
    const float* gW = (const float*)d_in[1];
    const float* w1 = (const float*)d_in[2];
    const float* b1 = (const float*)d_in[3];
    const float* w2 = (const float*)d_in[4];
    const float* b2 = (const float*)d_in[5];
    float* out = (float*)d_out;

    const int SMEM_BYTES = 3 * 32768;   // 96 KB dynamic
    cudaFuncSetAttribute(gemm_tc<H_DIM, D_DIM, true, 1>,
                         cudaFuncAttributeMaxDynamicSharedMemorySize, SMEM_BYTES);
    cudaFuncSetAttribute(gemm_tc<D_DIM, H_DIM, false, 2>,
                         cudaFuncAttributeMaxDynamicSharedMemorySize, SMEM_BYTES);

    init_kernel<<<1, 32>>>();
    prep_kernel<<<RB + W1T + W2T + ZYB, 256>>>(x, gW, w1, w2, out);

    gemm_tc<H_DIM, D_DIM, true, 1><<<dim3(H_DIM / 128, CAP / 128, E_NUM), 256, SMEM_BYTES>>>(
        b1, out, (long long)out_size);
    gemm_tc<D_DIM, H_DIM, false, 2><<<dim3(D_DIM / 128, CAP / 128, E_NUM * 2), 256, SMEM_BYTES>>>(
        b2, out, (long long)out_size);
}

// round 16
// speedup vs baseline: 1.0222x; 1.0222x over previous
#include <cuda_runtime.h>
#include <cuda_fp16.h>
#include <math.h>
#include <stdint.h>

#define BT      8192
#define D_DIM   1024
#define E_NUM   8
#define H_DIM   4096
#define CAP     (2*BT)
#define NSLOT   (2*BT)

#define RB      (BT / 32)                                 // 256 router blocks (32 tok/blk)
#define W1T     (E_NUM * (D_DIM / 64) * (H_DIM / 32))     // 16384
#define W2T     (E_NUM * (H_DIM / 64) * (D_DIM / 32))     // 16384
#define ZYB     2048                                      // zero-y blocks (16KB each)

// ---------------- device scratch ----------------
__device__ __half g_x[(size_t)BT * D_DIM];
__device__ __half g_w1t[(size_t)E_NUM * H_DIM * D_DIM];
__device__ __half g_w2t[(size_t)E_NUM * D_DIM * H_DIM];
__device__ __half g_h[(size_t)NSLOT * H_DIM];
__device__ int   g_slots[E_NUM * CAP];
__device__ float g_gp[NSLOT];
__device__ int   g_cnt[E_NUM];
__device__ float g_imp[E_NUM];
__device__ int   g_loadc[E_NUM];

// ---------------- PTX helpers ----------------
__device__ __forceinline__ uint32_t smem_u32(const void* p) {
    return (uint32_t)__cvta_generic_to_shared(p);
}
__device__ __forceinline__ void cp_async16(uint32_t dst, const void* src) {
    asm volatile("cp.async.cg.shared.global [%0], [%1], 16;" :: "r"(dst), "l"(src));
}
#define CP_COMMIT() asm volatile("cp.async.commit_group;" ::: "memory")
#define CP_WAIT1()  asm volatile("cp.async.wait_group 1;" ::: "memory")

__device__ __forceinline__ void ldmatrix_x4(uint32_t* r, uint32_t addr) {
    asm volatile("ldmatrix.sync.aligned.m8n8.x4.shared.b16 {%0,%1,%2,%3}, [%4];"
        : "=r"(r[0]), "=r"(r[1]), "=r"(r[2]), "=r"(r[3]) : "r"(addr));
}
__device__ __forceinline__ void mma_16816(float* d, const uint32_t* a,
                                          uint32_t b0, uint32_t b1) {
    asm volatile(
        "mma.sync.aligned.m16n8k16.row.col.f32.f16.f16.f32 "
        "{%0,%1,%2,%3}, {%4,%5,%6,%7}, {%8,%9}, {%0,%1,%2,%3};"
        : "+f"(d[0]), "+f"(d[1]), "+f"(d[2]), "+f"(d[3])
        : "r"(a[0]), "r"(a[1]), "r"(a[2]), "r"(a[3]), "r"(b0), "r"(b1));
}
__device__ __forceinline__ void red_add_f32(float* addr, float v) {
    asm volatile("red.global.add.f32 [%0], %1;" :: "l"(addr), "f"(v) : "memory");
}

// ---------------- init ----------------
__global__ void init_kernel() {
    int i = threadIdx.x;
    if (i < E_NUM) { g_cnt[i] = 0; g_imp[i] = 0.f; g_loadc[i] = 0; }
}

// ---------------- generic 64k x 32n convert+transpose tile ----------------
__device__ __forceinline__ void conv_tile(const float* __restrict__ W,
                                          __half* __restrict__ Wt,
                                          int K, int N, int idx, float* tile) {
    int tid = threadIdx.x;
    int tilesK = K / 64;
    int e  = idx / (tilesK * (N / 32));
    int r  = idx % (tilesK * (N / 32));
    int k0 = (r % tilesK) * 64;
    int n0 = (r / tilesK) * 32;
    const float* Wb = W + (size_t)e * K * N;
#pragma unroll
    for (int j = 0; j < 8; j++) {
        int i = tid + 256 * j;
        int k = i >> 5, n = i & 31;
        tile[k * 33 + n] = Wb[(size_t)(k0 + k) * N + n0 + n];
    }
    __syncthreads();
    int nn = tid >> 3;
    int kc = (tid & 7) * 8;
    __half h[8];
#pragma unroll
    for (int q = 0; q < 8; q++) h[q] = __float2half_rn(tile[(kc + q) * 33 + nn]);
    size_t o = ((size_t)e * N + n0 + nn) * K + k0 + kc;
    *(uint4*)&Wt[o] = *(uint4*)&h[0];
}

// ---------------- prep: router | w1 conv | w2 conv | zero-y by block range ----------------
__global__ void __launch_bounds__(256) prep_kernel(const float* __restrict__ x,
                                                   const float* __restrict__ gW,
                                                   const float* __restrict__ w1,
                                                   const float* __restrict__ w2,
                                                   float* __restrict__ y) {
    __shared__ float sW[E_NUM][D_DIM];   // router weights / conv tile
    __shared__ float s_imp[E_NUM];
    __shared__ int   s_load[E_NUM];
    int tid = threadIdx.x;
    int bid = blockIdx.x;

    if (bid >= RB) {
        int r = bid - RB;
        if (r < W1T) {
            conv_tile(w1, g_w1t, D_DIM, H_DIM, r, &sW[0][0]);
        } else if (r < W1T + W2T) {
            conv_tile(w2, g_w2t, H_DIM, D_DIM, r - W1T, &sW[0][0]);
        } else {
            size_t base = (size_t)(r - W1T - W2T) * 4096;     // floats
            float4* y4 = (float4*)(y + base);
#pragma unroll
            for (int j = 0; j < 4; j++)
                y4[tid + 256 * j] = make_float4(0.f, 0.f, 0.f, 0.f);
        }
        return;
    }

    // ---- router (+ fused x->fp16), 4 tokens per warp ----
    if (tid < E_NUM) { s_imp[tid] = 0.f; s_load[tid] = 0; }
    for (int i = tid; i < D_DIM * E_NUM; i += 256) {
        int d = i / E_NUM, e = i % E_NUM;
        sW[e][d] = gW[i];
    }
    __syncthreads();

    int warp = tid >> 5, lane = tid & 31;

#pragma unroll
    for (int tt = 0; tt < 4; tt++) {
        int t = (bid * 8 + warp) * 4 + tt;
        const float* xr = x + (size_t)t * D_DIM;

        float acc[E_NUM];
#pragma unroll
        for (int e = 0; e < E_NUM; e++) acc[e] = 0.f;
        for (int d4 = lane; d4 < D_DIM / 4; d4 += 32) {
            float4 v = ((const float4*)xr)[d4];
            float f[4] = {v.x, v.y, v.z, v.w};
            __half h[4];
#pragma unroll
            for (int q = 0; q < 4; q++) {
                h[q] = __float2half_rn(f[q]);
#pragma unroll
                for (int e = 0; e < E_NUM; e++)
                    acc[e] = fmaf(f[q], sW[e][d4 * 4 + q], acc[e]);
            }
            ((uint2*)g_x)[(size_t)t * (D_DIM / 4) + d4] = *(uint2*)&h[0];
        }
#pragma unroll
        for (int off = 16; off > 0; off >>= 1) {
#pragma unroll
            for (int e = 0; e < E_NUM; e++)
                acc[e] += __shfl_xor_sync(0xffffffffu, acc[e], off);
        }

        if (lane == 0) {
            float mx = acc[0];
#pragma unroll
            for (int e = 1; e < E_NUM; e++) mx = fmaxf(mx, acc[e]);
            float p[E_NUM], s = 0.f;
#pragma unroll
            for (int e = 0; e < E_NUM; e++) { p[e] = expf(acc[e] - mx); s += p[e]; }
            float inv = 1.f / s;
#pragma unroll
            for (int e = 0; e < E_NUM; e++) p[e] *= inv;

            int e1 = 0; float v1 = p[0];
#pragma unroll
            for (int e = 1; e < E_NUM; e++) if (p[e] > v1) { v1 = p[e]; e1 = e; }
            int e2 = -1; float v2 = -1.f;
#pragma unroll
            for (int e = 0; e < E_NUM; e++) if (e != e1 && p[e] > v2) { v2 = p[e]; e2 = e; }

            float ginv = 1.f / (v1 + v2);
            g_gp[2 * t]     = v1 * ginv;
            g_gp[2 * t + 1] = v2 * ginv;

            int p1 = atomicAdd(&g_cnt[e1], 1); g_slots[e1 * CAP + p1] = 2 * t;
            int p2 = atomicAdd(&g_cnt[e2], 1); g_slots[e2 * CAP + p2] = 2 * t + 1;
#pragma unroll
            for (int e = 0; e < E_NUM; e++) atomicAdd(&s_imp[e], p[e]);
            atomicAdd(&s_load[e1], 1);
        }
    }
    __syncthreads();
    if (tid < E_NUM) {
        atomicAdd(&g_imp[tid], s_imp[tid]);
        atomicAdd(&g_loadc[tid], s_load[tid]);
    }
}

// ---------------- mma.sync grouped GEMM ----------------
// CTA tile 128x128, K-chunk 64, 3-stage cp.async (96KB), 2 CTAs/SM.
// Single __syncthreads per chunk. PHASE2 fuses gate-weighted reduce into y + aux.
template <int N_TOT, int K_SIZE, bool PHASE1>
__global__ void __launch_bounds__(256, 2) gemm_tc(const float* __restrict__ bias,
                                                  float* __restrict__ yout,
                                                  long long out_size) {
    int e   = blockIdx.z;
    int cnt = g_cnt[e];
    int m0  = blockIdx.y * 128;
    int n0  = blockIdx.x * 128;
    int tid = threadIdx.x;

    // fold aux-loss write into one CTA of gemm2 (before any early exit)
    if (!PHASE1 && blockIdx.x == 0 && blockIdx.y == 0 && blockIdx.z == 0 && tid == 0) {
        float aux = 0.f;
        const float invBT = 1.f / (float)BT;
#pragma unroll
        for (int q = 0; q < E_NUM; q++)
            aux += (g_imp[q] * invBT) * ((float)g_loadc[q] * invBT);
        aux *= (float)E_NUM * 0.01f;
        yout[out_size - 1] = aux;
    }
    if (m0 >= cnt) return;

    extern __shared__ char smem[];
    uint32_t sb = smem_u32(smem);
    const int STAGE = 32768;
    const int AOF = 0, BOF = 16384;

    __shared__ int   sSlot[128];
    __shared__ float sBias[128];
    __shared__ float sGp[128];

    int lane = tid & 31;
    int w    = tid >> 5;
    int wm   = w >> 2;
    int wn   = w & 3;

    if (tid < 128) {
        int m = m0 + tid;
        int s = (m < cnt) ? g_slots[e * CAP + m] : -1;
        sSlot[tid] = s;
        sBias[tid] = bias[(size_t)e * N_TOT + n0 + tid];
        if (!PHASE1) sGp[tid] = (s >= 0) ? g_gp[s] : 0.f;
    }
    __syncthreads();

    if (cnt - m0 < 128) {
#pragma unroll
        for (int s = 0; s < 3; s++) {
            uint32_t base = sb + s * STAGE + AOF;
            for (int off = tid * 16; off < 16384; off += 256 * 16)
                asm volatile("st.shared.v4.b32 [%0], {%1,%1,%1,%1};" :: "r"(base + off), "r"(0) : "memory");
        }
        __syncthreads();
    }

    const __half* Ap = PHASE1 ? g_x   : g_h;
    const __half* Bp = PHASE1 ? g_w1t : g_w2t;

    const char* aP[4];
    const char* bP[4];
    bool aval[4];
    uint32_t dsw[4];
    int colB = (tid & 7) * 16;
#pragma unroll
    for (int j = 0; j < 4; j++) {
        int row = (tid >> 3) + j * 32;
        int s   = sSlot[row];
        aval[j] = (s >= 0);
        size_t arow = 0;
        if (aval[j]) arow = PHASE1 ? (size_t)(s >> 1) : (size_t)s;
        aP[j] = (const char*)(Ap + arow * K_SIZE) + colB;
        size_t nrow = (size_t)e * N_TOT + n0 + row;
        bP[j] = (const char*)(Bp + nrow * K_SIZE) + colB;
        uint32_t off = (uint32_t)row * 128 + colB;
        dsw[j] = off ^ ((off >> 3) & 0x70);
    }

#define LOAD_CHUNK(c) do { \
        uint32_t base_ = sb + ((c) % 3) * STAGE; \
        size_t kb_ = (size_t)(c) * 128; \
        _Pragma("unroll") \
        for (int j = 0; j < 4; j++) { \
            if (aval[j]) cp_async16(base_ + AOF + dsw[j], aP[j] + kb_); \
            cp_async16(base_ + BOF + dsw[j], bP[j] + kb_); \
        } \
    } while (0)

    int lrow = ((lane >> 3) & 1) * 8 + (lane & 7);
    int lkb  = (lane >> 4) * 16;

    float acc[4][4][4];
#pragma unroll
    for (int i = 0; i < 4; i++)
#pragma unroll
        for (int j = 0; j < 4; j++)
#pragma unroll
            for (int q = 0; q < 4; q++) acc[i][j][q] = 0.f;

    constexpr int C = K_SIZE / 64;
    LOAD_CHUNK(0); CP_COMMIT();
    LOAD_CHUNK(1); CP_COMMIT();

    for (int c = 0; c < C; c++) {
        uint32_t base = sb + (c % 3) * STAGE;
        CP_WAIT1();
        __syncthreads();
        if (c + 2 < C) LOAD_CHUNK(c + 2);
        CP_COMMIT();

#pragma unroll
        for (int kk = 0; kk < 4; kk++) {
            int kb = kk * 32 + lkb;
            uint32_t ah[4][4];
#pragma unroll
            for (int mi = 0; mi < 4; mi++) {
                uint32_t off = (uint32_t)(wm * 64 + mi * 16 + lrow) * 128 + kb;
                uint32_t sw  = off ^ ((off >> 3) & 0x70);
                ldmatrix_x4(ah[mi], base + AOF + sw);
            }
            uint32_t bh[2][4];
#pragma unroll
            for (int ng = 0; ng < 2; ng++) {
                uint32_t off = (uint32_t)(wn * 32 + ng * 16 + lrow) * 128 + kb;
                uint32_t sw  = off ^ ((off >> 3) & 0x70);
                ldmatrix_x4(bh[ng], base + BOF + sw);
            }
#pragma unroll
            for (int mi = 0; mi < 4; mi++) {
#pragma unroll
                for (int ng = 0; ng < 2; ng++) {
#pragma unroll
                    for (int jj = 0; jj < 2; jj++) {
                        int nj = ng * 2 + jj;
                        mma_16816(acc[mi][nj], ah[mi], bh[ng][jj], bh[ng][jj + 2]);
                    }
                }
            }
        }
    }
#undef LOAD_CHUNK

    // ---------------- epilogue ----------------
#pragma unroll
    for (int mi = 0; mi < 4; mi++) {
#pragma unroll
        for (int h2 = 0; h2 < 2; h2++) {
            int rloc = wm * 64 + mi * 16 + h2 * 8 + (lane >> 2);
            int slot = sSlot[rloc];
            if (slot < 0) continue;
            float gp = PHASE1 ? 0.f : sGp[rloc];
#pragma unroll
            for (int nj = 0; nj < 4; nj++) {
                int cl = wn * 32 + nj * 8 + (lane & 3) * 2;
                float v0 = acc[mi][nj][h2 * 2 + 0] + sBias[cl];
                float v1 = acc[mi][nj][h2 * 2 + 1] + sBias[cl + 1];
                if (PHASE1) {
                    v0 = fmaxf(v0, 0.f);
                    v1 = fmaxf(v1, 0.f);
                    __half2 hp;
                    hp.x = __float2half_rn(v0);
                    hp.y = __float2half_rn(v1);
                    size_t bo = (size_t)slot * H_DIM + n0 + cl;
                    *(__half2*)&g_h[bo] = hp;
                } else {
                    size_t bo = (size_t)(slot >> 1) * D_DIM + n0 + cl;
                    red_add_f32(&yout[bo],     gp * v0);
                    red_add_f32(&yout[bo + 1], gp * v1);
                }
            }
        }
    }
}

// ---------------- launch ----------------
extern "C" void kernel_launch(void* const* d_in, const int* in_sizes, int n_in,
                              void* d_out, int out_size) {
    const float* x  = (const float*)d_in[0];
    const float* gW = (const float*)d_in[1];
    const float* w1 = (const float*)d_in[2];
    const float* b1 = (const float*)d_in[3];
    const float* w2 = (const float*)d_in[4];
    const float* b2 = (const float*)d_in[5];
    float* out = (float*)d_out;

    const int SMEM_BYTES = 3 * 32768;   // 96 KB dynamic
    cudaFuncSetAttribute(gemm_tc<H_DIM, D_DIM, true>,
                         cudaFuncAttributeMaxDynamicSharedMemorySize, SMEM_BYTES);
    cudaFuncSetAttribute(gemm_tc<D_DIM, H_DIM, false>,
                         cudaFuncAttributeMaxDynamicSharedMemorySize, SMEM_BYTES);

    init_kernel<<<1, 32>>>();
    prep_kernel<<<RB + W1T + W2T + ZYB, 256>>>(x, gW, w1, w2, out);

    gemm_tc<H_DIM, D_DIM, true ><<<dim3(H_DIM / 128, CAP / 128, E_NUM), 256, SMEM_BYTES>>>(
        b1, out, (long long)out_size);
    gemm_tc<D_DIM, H_DIM, false><<<dim3(D_DIM / 128, CAP / 128, E_NUM), 256, SMEM_BYTES>>>(
        b2, out, (long long)out_size);
}

// round 17
// speedup vs baseline: 1.0285x; 1.0062x over previous
#include <cuda_runtime.h>
#include <cuda_fp16.h>
#include <math.h>
#include <stdint.h>

#define BT      8192
#define D_DIM   1024
#define E_NUM   8
#define H_DIM   4096
#define CAP     (2*BT)
#define NSLOT   (2*BT)

#define RB      (BT / 32)                                 // 256 router blocks (32 tok/blk)
#define W1T     (E_NUM * (D_DIM / 64) * (H_DIM / 32))     // 16384
#define W2T     (E_NUM * (H_DIM / 64) * (D_DIM / 32))     // 16384
#define ZYB     2048                                      // zero-y blocks (16KB each)

// ---------------- device scratch ----------------
__device__ __half g_x[(size_t)BT * D_DIM];
__device__ __half g_w1t[(size_t)E_NUM * H_DIM * D_DIM];
__device__ __half g_w2t[(size_t)E_NUM * D_DIM * H_DIM];
__device__ __half g_h[(size_t)NSLOT * H_DIM];
__device__ int   g_slots[E_NUM * CAP];
__device__ float g_gp[NSLOT];
__device__ int   g_cnt[E_NUM];
__device__ float g_imp[E_NUM];
__device__ int   g_loadc[E_NUM];

// ---------------- PTX helpers ----------------
__device__ __forceinline__ uint32_t smem_u32(const void* p) {
    return (uint32_t)__cvta_generic_to_shared(p);
}
__device__ __forceinline__ void cp_async16(uint32_t dst, const void* src) {
    asm volatile("cp.async.cg.shared.global [%0], [%1], 16;" :: "r"(dst), "l"(src));
}
#define CP_COMMIT() asm volatile("cp.async.commit_group;" ::: "memory")
#define CP_WAIT1()  asm volatile("cp.async.wait_group 1;" ::: "memory")

__device__ __forceinline__ void ldmatrix_x4(uint32_t* r, uint32_t addr) {
    asm volatile("ldmatrix.sync.aligned.m8n8.x4.shared.b16 {%0,%1,%2,%3}, [%4];"
        : "=r"(r[0]), "=r"(r[1]), "=r"(r[2]), "=r"(r[3]) : "r"(addr));
}
__device__ __forceinline__ void mma_16816(float* d, const uint32_t* a,
                                          uint32_t b0, uint32_t b1) {
    asm volatile(
        "mma.sync.aligned.m16n8k16.row.col.f32.f16.f16.f32 "
        "{%0,%1,%2,%3}, {%4,%5,%6,%7}, {%8,%9}, {%0,%1,%2,%3};"
        : "+f"(d[0]), "+f"(d[1]), "+f"(d[2]), "+f"(d[3])
        : "r"(a[0]), "r"(a[1]), "r"(a[2]), "r"(a[3]), "r"(b0), "r"(b1));
}
__device__ __forceinline__ void red_add_v2_f32(float* addr, float v0, float v1) {
    asm volatile("red.global.add.v2.f32 [%0], {%1, %2};"
        :: "l"(addr), "f"(v0), "f"(v1) : "memory");
}

// ---------------- init ----------------
__global__ void init_kernel() {
    int i = threadIdx.x;
    if (i < E_NUM) { g_cnt[i] = 0; g_imp[i] = 0.f; g_loadc[i] = 0; }
}

// ---------------- generic 64k x 32n convert+transpose tile ----------------
__device__ __forceinline__ void conv_tile(const float* __restrict__ W,
                                          __half* __restrict__ Wt,
                                          int K, int N, int idx, float* tile) {
    int tid = threadIdx.x;
    int tilesK = K / 64;
    int e  = idx / (tilesK * (N / 32));
    int r  = idx % (tilesK * (N / 32));
    int k0 = (r % tilesK) * 64;
    int n0 = (r / tilesK) * 32;
    const float* Wb = W + (size_t)e * K * N;
#pragma unroll
    for (int j = 0; j < 8; j++) {
        int i = tid + 256 * j;
        int k = i >> 5, n = i & 31;
        tile[k * 33 + n] = Wb[(size_t)(k0 + k) * N + n0 + n];
    }
    __syncthreads();
    int nn = tid >> 3;
    int kc = (tid & 7) * 8;
    __half h[8];
#pragma unroll
    for (int q = 0; q < 8; q++) h[q] = __float2half_rn(tile[(kc + q) * 33 + nn]);
    size_t o = ((size_t)e * N + n0 + nn) * K + k0 + kc;
    *(uint4*)&Wt[o] = *(uint4*)&h[0];
}

// ---------------- prep: router | w1 conv | w2 conv | zero-y by block range ----------------
__global__ void __launch_bounds__(256) prep_kernel(const float* __restrict__ x,
                                                   const float* __restrict__ gW,
                                                   const float* __restrict__ w1,
                                                   const float* __restrict__ w2,
                                                   float* __restrict__ y) {
    __shared__ float sW[E_NUM][D_DIM];   // router weights / conv tile
    __shared__ float s_imp[E_NUM];
    __shared__ int   s_load[E_NUM];
    int tid = threadIdx.x;
    int bid = blockIdx.x;

    if (bid >= RB) {
        int r = bid - RB;
        if (r < W1T) {
            conv_tile(w1, g_w1t, D_DIM, H_DIM, r, &sW[0][0]);
        } else if (r < W1T + W2T) {
            conv_tile(w2, g_w2t, H_DIM, D_DIM, r - W1T, &sW[0][0]);
        } else {
            size_t base = (size_t)(r - W1T - W2T) * 4096;     // floats
            float4* y4 = (float4*)(y + base);
#pragma unroll
            for (int j = 0; j < 4; j++)
                y4[tid + 256 * j] = make_float4(0.f, 0.f, 0.f, 0.f);
        }
        return;
    }

    // ---- router (+ fused x->fp16), 4 tokens per warp ----
    if (tid < E_NUM) { s_imp[tid] = 0.f; s_load[tid] = 0; }
    for (int i = tid; i < D_DIM * E_NUM; i += 256) {
        int d = i / E_NUM, e = i % E_NUM;
        sW[e][d] = gW[i];
    }
    __syncthreads();

    int warp = tid >> 5, lane = tid & 31;

#pragma unroll
    for (int tt = 0; tt < 4; tt++) {
        int t = (bid * 8 + warp) * 4 + tt;
        const float* xr = x + (size_t)t * D_DIM;

        float acc[E_NUM];
#pragma unroll
        for (int e = 0; e < E_NUM; e++) acc[e] = 0.f;
        for (int d4 = lane; d4 < D_DIM / 4; d4 += 32) {
            float4 v = ((const float4*)xr)[d4];
            float f[4] = {v.x, v.y, v.z, v.w};
            __half h[4];
#pragma unroll
            for (int q = 0; q < 4; q++) {
                h[q] = __float2half_rn(f[q]);
#pragma unroll
                for (int e = 0; e < E_NUM; e++)
                    acc[e] = fmaf(f[q], sW[e][d4 * 4 + q], acc[e]);
            }
            ((uint2*)g_x)[(size_t)t * (D_DIM / 4) + d4] = *(uint2*)&h[0];
        }
#pragma unroll
        for (int off = 16; off > 0; off >>= 1) {
#pragma unroll
            for (int e = 0; e < E_NUM; e++)
                acc[e] += __shfl_xor_sync(0xffffffffu, acc[e], off);
        }

        if (lane == 0) {
            float mx = acc[0];
#pragma unroll
            for (int e = 1; e < E_NUM; e++) mx = fmaxf(mx, acc[e]);
            float p[E_NUM], s = 0.f;
#pragma unroll
            for (int e = 0; e < E_NUM; e++) { p[e] = expf(acc[e] - mx); s += p[e]; }
            float inv = 1.f / s;
#pragma unroll
            for (int e = 0; e < E_NUM; e++) p[e] *= inv;

            int e1 = 0; float v1 = p[0];
#pragma unroll
            for (int e = 1; e < E_NUM; e++) if (p[e] > v1) { v1 = p[e]; e1 = e; }
            int e2 = -1; float v2 = -1.f;
#pragma unroll
            for (int e = 0; e < E_NUM; e++) if (e != e1 && p[e] > v2) { v2 = p[e]; e2 = e; }

            float ginv = 1.f / (v1 + v2);
            g_gp[2 * t]     = v1 * ginv;
            g_gp[2 * t + 1] = v2 * ginv;

            int p1 = atomicAdd(&g_cnt[e1], 1); g_slots[e1 * CAP + p1] = 2 * t;
            int p2 = atomicAdd(&g_cnt[e2], 1); g_slots[e2 * CAP + p2] = 2 * t + 1;
#pragma unroll
            for (int e = 0; e < E_NUM; e++) atomicAdd(&s_imp[e], p[e]);
            atomicAdd(&s_load[e1], 1);
        }
    }
    __syncthreads();
    if (tid < E_NUM) {
        atomicAdd(&g_imp[tid], s_imp[tid]);
        atomicAdd(&g_loadc[tid], s_load[tid]);
    }
}

// ---------------- mma.sync grouped GEMM ----------------
// CTA tile 128x128, K-chunk 64, 3-stage cp.async (96KB), 2 CTAs/SM.
// Single __syncthreads per chunk. PHASE2 fuses gate-weighted v2-REDG into y + aux.
template <int N_TOT, int K_SIZE, bool PHASE1>
__global__ void __launch_bounds__(256, 2) gemm_tc(const float* __restrict__ bias,
                                                  float* __restrict__ yout,
                                                  long long out_size) {
    int e   = blockIdx.z;
    int cnt = g_cnt[e];
    int m0  = blockIdx.y * 128;
    int n0  = blockIdx.x * 128;
    int tid = threadIdx.x;

    // fold aux-loss write into one CTA of gemm2 (before any early exit)
    if (!PHASE1 && blockIdx.x == 0 && blockIdx.y == 0 && blockIdx.z == 0 && tid == 0) {
        float aux = 0.f;
        const float invBT = 1.f / (float)BT;
#pragma unroll
        for (int q = 0; q < E_NUM; q++)
            aux += (g_imp[q] * invBT) * ((float)g_loadc[q] * invBT);
        aux *= (float)E_NUM * 0.01f;
        yout[out_size - 1] = aux;
    }
    if (m0 >= cnt) return;

    extern __shared__ char smem[];
    uint32_t sb = smem_u32(smem);
    const int STAGE = 32768;
    const int AOF = 0, BOF = 16384;

    __shared__ int   sSlot[128];
    __shared__ float sBias[128];
    __shared__ float sGp[128];

    int lane = tid & 31;
    int w    = tid >> 5;
    int wm   = w >> 2;
    int wn   = w & 3;

    if (tid < 128) {
        int m = m0 + tid;
        int s = (m < cnt) ? g_slots[e * CAP + m] : -1;
        sSlot[tid] = s;
        sBias[tid] = bias[(size_t)e * N_TOT + n0 + tid];
        if (!PHASE1) sGp[tid] = (s >= 0) ? g_gp[s] : 0.f;
    }
    __syncthreads();

    if (cnt - m0 < 128) {
#pragma unroll
        for (int s = 0; s < 3; s++) {
            uint32_t base = sb + s * STAGE + AOF;
            for (int off = tid * 16; off < 16384; off += 256 * 16)
                asm volatile("st.shared.v4.b32 [%0], {%1,%1,%1,%1};" :: "r"(base + off), "r"(0) : "memory");
        }
        __syncthreads();
    }

    const __half* Ap = PHASE1 ? g_x   : g_h;
    const __half* Bp = PHASE1 ? g_w1t : g_w2t;

    const char* aP[4];
    const char* bP[4];
    bool aval[4];
    uint32_t dsw[4];
    int colB = (tid & 7) * 16;
#pragma unroll
    for (int j = 0; j < 4; j++) {
        int row = (tid >> 3) + j * 32;
        int s   = sSlot[row];
        aval[j] = (s >= 0);
        size_t arow = 0;
        if (aval[j]) arow = PHASE1 ? (size_t)(s >> 1) : (size_t)s;
        aP[j] = (const char*)(Ap + arow * K_SIZE) + colB;
        size_t nrow = (size_t)e * N_TOT + n0 + row;
        bP[j] = (const char*)(Bp + nrow * K_SIZE) + colB;
        uint32_t off = (uint32_t)row * 128 + colB;
        dsw[j] = off ^ ((off >> 3) & 0x70);
    }

#define LOAD_CHUNK(c) do { \
        uint32_t base_ = sb + ((c) % 3) * STAGE; \
        size_t kb_ = (size_t)(c) * 128; \
        _Pragma("unroll") \
        for (int j = 0; j < 4; j++) { \
            if (aval[j]) cp_async16(base_ + AOF + dsw[j], aP[j] + kb_); \
            cp_async16(base_ + BOF + dsw[j], bP[j] + kb_); \
        } \
    } while (0)

    int lrow = ((lane >> 3) & 1) * 8 + (lane & 7);
    int lkb  = (lane >> 4) * 16;

    float acc[4][4][4];
#pragma unroll
    for (int i = 0; i < 4; i++)
#pragma unroll
        for (int j = 0; j < 4; j++)
#pragma unroll
            for (int q = 0; q < 4; q++) acc[i][j][q] = 0.f;

    constexpr int C = K_SIZE / 64;
    LOAD_CHUNK(0); CP_COMMIT();
    LOAD_CHUNK(1); CP_COMMIT();

    for (int c = 0; c < C; c++) {
        uint32_t base = sb + (c % 3) * STAGE;
        CP_WAIT1();
        __syncthreads();
        if (c + 2 < C) LOAD_CHUNK(c + 2);
        CP_COMMIT();

#pragma unroll
        for (int kk = 0; kk < 4; kk++) {
            int kb = kk * 32 + lkb;
            uint32_t ah[4][4];
#pragma unroll
            for (int mi = 0; mi < 4; mi++) {
                uint32_t off = (uint32_t)(wm * 64 + mi * 16 + lrow) * 128 + kb;
                uint32_t sw  = off ^ ((off >> 3) & 0x70);
                ldmatrix_x4(ah[mi], base + AOF + sw);
            }
            uint32_t bh[2][4];
#pragma unroll
            for (int ng = 0; ng < 2; ng++) {
                uint32_t off = (uint32_t)(wn * 32 + ng * 16 + lrow) * 128 + kb;
                uint32_t sw  = off ^ ((off >> 3) & 0x70);
                ldmatrix_x4(bh[ng], base + BOF + sw);
            }
#pragma unroll
            for (int mi = 0; mi < 4; mi++) {
#pragma unroll
                for (int ng = 0; ng < 2; ng++) {
#pragma unroll
                    for (int jj = 0; jj < 2; jj++) {
                        int nj = ng * 2 + jj;
                        mma_16816(acc[mi][nj], ah[mi], bh[ng][jj], bh[ng][jj + 2]);
                    }
                }
            }
        }
    }
#undef LOAD_CHUNK

    // ---------------- epilogue ----------------
#pragma unroll
    for (int mi = 0; mi < 4; mi++) {
#pragma unroll
        for (int h2 = 0; h2 < 2; h2++) {
            int rloc = wm * 64 + mi * 16 + h2 * 8 + (lane >> 2);
            int slot = sSlot[rloc];
            if (slot < 0) continue;
            float gp = PHASE1 ? 0.f : sGp[rloc];
#pragma unroll
            for (int nj = 0; nj < 4; nj++) {
                int cl = wn * 32 + nj * 8 + (lane & 3) * 2;
                float v0 = acc[mi][nj][h2 * 2 + 0] + sBias[cl];
                float v1 = acc[mi][nj][h2 * 2 + 1] + sBias[cl + 1];
                if (PHASE1) {
                    v0 = fmaxf(v0, 0.f);
                    v1 = fmaxf(v1, 0.f);
                    __half2 hp;
                    hp.x = __float2half_rn(v0);
                    hp.y = __float2half_rn(v1);
                    size_t bo = (size_t)slot * H_DIM + n0 + cl;
                    *(__half2*)&g_h[bo] = hp;
                } else {
                    size_t bo = (size_t)(slot >> 1) * D_DIM + n0 + cl;
                    red_add_v2_f32(&yout[bo], gp * v0, gp * v1);
                }
            }
        }
    }
}

// ---------------- launch ----------------
extern "C" void kernel_launch(void* const* d_in, const int* in_sizes, int n_in,
                              void* d_out, int out_size) {
    const float* x  = (const float*)d_in[0];
    const float* gW = (const float*)d_in[1];
    const float* w1 = (const float*)d_in[2];
    const float* b1 = (const float*)d_in[3];
    const float* w2 = (const float*)d_in[4];
    const float* b2 = (const float*)d_in[5];
    float* out = (float*)d_out;

    const int SMEM_BYTES = 3 * 32768;   // 96 KB dynamic
    cudaFuncSetAttribute(gemm_tc<H_DIM, D_DIM, true>,
                         cudaFuncAttributeMaxDynamicSharedMemorySize, SMEM_BYTES);
    cudaFuncSetAttribute(gemm_tc<D_DIM, H_DIM, false>,
                         cudaFuncAttributeMaxDynamicSharedMemorySize, SMEM_BYTES);

    init_kernel<<<1, 32>>>();
    prep_kernel<<<RB + W1T + W2T + ZYB, 256>>>(x, gW, w1, w2, out);

    gemm_tc<H_DIM, D_DIM, true ><<<dim3(H_DIM / 128, CAP / 128, E_NUM), 256, SMEM_BYTES>>>(
        b1, out, (long long)out_size);
    gemm_tc<D_DIM, H_DIM, false><<<dim3(D_DIM / 128, CAP / 128, E_NUM), 256, SMEM_BYTES>>>(
        b2, out, (long long)out_size);
}